// round 17
// baseline (speedup 1.0000x reference)
#include <cuda_runtime.h>
#include <cuda_bf16.h>
#include <cstdint>

// Two-phase: (1) convert x->patch matrix X[kk=144][pos=3200] as bf16 hi/lo pairs
// (split precision) + W[192][144] hi/lo into __device__ scratch;
// (2) dense GEMM D[i,pos] = sum_kk W[i,kk]*X[kk,pos] via mma.sync bf16
// (3 cross terms: WhXh + WhXl + WlXh, fp32 accum).

#define POSP 3200        // padded pos (3136 real)
#define XST2 136         // smem X row stride (bf16)
#define WST2 152         // smem W row stride (bf16)
#define NT 256

__device__ __nv_bfloat16 g_X[2 * 144 * POSP];   // [s][kk][pos]
__device__ __nv_bfloat16 g_W[2 * 192 * 144];    // [s][i][kk]

__device__ __forceinline__ uint32_t smem_u32(const void* p) {
    uint32_t a;
    asm("{ .reg .u64 t; cvta.to.shared.u64 t, %1; cvt.u32.u64 %0, t; }" : "=r"(a) : "l"(p));
    return a;
}
__device__ __forceinline__ uint32_t pk(__nv_bfloat16 a, __nv_bfloat16 b) {
    return (uint32_t)__bfloat16_as_ushort(a) | ((uint32_t)__bfloat16_as_ushort(b) << 16);
}
#define LDMX4(r, addr) \
    asm volatile("ldmatrix.sync.aligned.m8n8.x4.shared.b16 {%0,%1,%2,%3}, [%4];" \
                 : "=r"((r)[0]), "=r"((r)[1]), "=r"((r)[2]), "=r"((r)[3]) : "r"(addr))
#define LDMX2T(r, addr) \
    asm volatile("ldmatrix.sync.aligned.m8n8.x2.trans.shared.b16 {%0,%1}, [%2];" \
                 : "=r"((r)[0]), "=r"((r)[1]) : "r"(addr))
#define MMA(d, a, b) \
    asm volatile("mma.sync.aligned.m16n8k16.row.col.f32.bf16.bf16.f32 " \
                 "{%0,%1,%2,%3}, {%4,%5,%6,%7}, {%8,%9}, {%0,%1,%2,%3};" \
                 : "+f"((d)[0]), "+f"((d)[1]), "+f"((d)[2]), "+f"((d)[3]) \
                 : "r"((a)[0]), "r"((a)[1]), "r"((a)[2]), "r"((a)[3]), \
                   "r"((b)[0]), "r"((b)[1]))

// ---------------- phase 1: converter ----------------
#define NA (144 * 56 * 7)       // X fill groups (8 m each)
#define NB (144 * 8)            // X pad-zero groups
#define NC (192 * 18)           // W fill groups (8 kk each)

__global__ __launch_bounds__(NT)
void conv_kernel(const float* __restrict__ x, const float* __restrict__ W)
{
    int g = blockIdx.x * NT + threadIdx.x;
    if (g < NA) {
        int q    = g % 7;
        int rest = g / 7;
        int h    = rest % 56;
        int kk   = rest / 56;
        int j = kk / 3, k = kk - 3 * j;
        int o = h % 7;
        int r = o + k - 1;
        int m0 = q * 8;
        float4 v0 = make_float4(0.f, 0.f, 0.f, 0.f), v1 = v0;
        if (r >= 0 && r < 7) {
            const float* src = x + (j * 56 + h + k - 1) * 56 + m0;
            v0 = *(const float4*)src;
            v1 = *(const float4*)(src + 4);
        }
        const float vv[8] = {v0.x, v0.y, v0.z, v0.w, v1.x, v1.y, v1.z, v1.w};
        __nv_bfloat16 hi8[8], lo8[8];
        #pragma unroll
        for (int e = 0; e < 8; ++e) {
            hi8[e] = __float2bfloat16_rn(vv[e]);
            lo8[e] = __float2bfloat16_rn(vv[e] - __bfloat162float(hi8[e]));
        }
        int off = kk * POSP + h * 56 + m0;
        *(uint4*)&g_X[off] = make_uint4(pk(hi8[0], hi8[1]), pk(hi8[2], hi8[3]),
                                        pk(hi8[4], hi8[5]), pk(hi8[6], hi8[7]));
        *(uint4*)&g_X[144 * POSP + off] = make_uint4(pk(lo8[0], lo8[1]), pk(lo8[2], lo8[3]),
                                                     pk(lo8[4], lo8[5]), pk(lo8[6], lo8[7]));
    } else if (g < NA + NB) {
        int gg = g - NA;
        int kk = gg >> 3, q = gg & 7;
        int off = kk * POSP + 3136 + q * 8;
        uint4 z = make_uint4(0, 0, 0, 0);
        *(uint4*)&g_X[off] = z;
        *(uint4*)&g_X[144 * POSP + off] = z;
    } else if (g < NA + NB + NC) {
        int gg = g - NA - NB;
        int ii = gg / 18, q = gg - ii * 18;
        int kk0 = q * 8;
        const float* src = W + ii * 144 + kk0;
        float4 v0 = *(const float4*)src, v1 = *(const float4*)(src + 4);
        const float vv[8] = {v0.x, v0.y, v0.z, v0.w, v1.x, v1.y, v1.z, v1.w};
        __nv_bfloat16 hi8[8], lo8[8];
        #pragma unroll
        for (int e = 0; e < 8; ++e) {
            hi8[e] = __float2bfloat16_rn(vv[e]);
            lo8[e] = __float2bfloat16_rn(vv[e] - __bfloat162float(hi8[e]));
        }
        int off = ii * 144 + kk0;
        *(uint4*)&g_W[off] = make_uint4(pk(hi8[0], hi8[1]), pk(hi8[2], hi8[3]),
                                        pk(hi8[4], hi8[5]), pk(hi8[6], hi8[7]));
        *(uint4*)&g_W[192 * 144 + off] = make_uint4(pk(lo8[0], lo8[1]), pk(lo8[2], lo8[3]),
                                                    pk(lo8[4], lo8[5]), pk(lo8[6], lo8[7]));
    }
}

// ---------------- phase 2: GEMM ----------------
#define SM_XHI 0
#define SM_XLO (144 * XST2 * 2)                 // 39168
#define SM_WHI (2 * 144 * XST2 * 2)             // 78336
#define SM_WLO (SM_WHI + 32 * WST2 * 2)         // 88064
#define SM_TOTAL (SM_WLO + 32 * WST2 * 2)       // 97792 B

__global__ __launch_bounds__(NT, 1)
void gemm_kernel(float* __restrict__ out)
{
    extern __shared__ char smem[];
    const int tid  = threadIdx.x;
    const int pos0 = blockIdx.x * 128;      // 0..3072 step 128 (25 tiles)
    const int i0   = blockIdx.y * 32;       // 0..160 step 32
    const uint32_t sb = smem_u32(smem);

    // ---- copy X tile [2][144][128] from scratch, uint4 granular ----
    {
        __nv_bfloat16* xsm = (__nv_bfloat16*)smem;   // hi at 0, lo at 144*XST2
        #pragma unroll
        for (int it = 0; it < (2 * 144 * 16) / NT; ++it) {   // 18 iters
            int idx = tid + it * NT;                 // 0..4607
            int s  = idx / 2304;
            int rr = (idx - s * 2304) >> 4;
            int c  = idx & 15;
            uint4 v = *(const uint4*)&g_X[s * (144 * POSP) + rr * POSP + pos0 + c * 8];
            *(uint4*)&xsm[s * (144 * XST2) + rr * XST2 + c * 8] = v;
        }
    }
    // ---- copy W tile [2][32][144] ----
    {
        __nv_bfloat16* wsm = (__nv_bfloat16*)(smem + SM_WHI);
        #pragma unroll
        for (int it = 0; it < 5; ++it) {
            int idx = tid + it * NT;                 // < 1152
            if (idx < 2 * 32 * 18) {
                int s  = idx / 576;
                int rr = (idx - s * 576) / 18;
                int c  = idx - s * 576 - rr * 18;
                uint4 v = *(const uint4*)&g_W[s * (192 * 144) + (i0 + rr) * 144 + c * 8];
                *(uint4*)&wsm[s * (32 * WST2) + rr * WST2 + c * 8] = v;
            }
        }
    }
    __syncthreads();

    // ---- warp mma mainloop: mt=2 (32 i), nt=2 per warp (16 pos) ----
    const int warp = tid >> 5;
    const int lane = tid & 31;
    const int lr16 = lane & 15;
    const int lc   = lane >> 4;

    uint32_t aHb[2], aLb[2];
    #pragma unroll
    for (int mt = 0; mt < 2; ++mt) {
        uint32_t roff = (uint32_t)((mt * 16 + lr16) * WST2 + lc * 8) * 2u;
        aHb[mt] = sb + SM_WHI + roff;
        aLb[mt] = sb + SM_WLO + roff;
    }
    uint32_t bHb[2], bLb[2];
    #pragma unroll
    for (int nti = 0; nti < 2; ++nti) {
        uint32_t boff = (uint32_t)(lr16 * XST2 + (warp * 2 + nti) * 8) * 2u;
        bHb[nti] = sb + SM_XHI + boff;
        bLb[nti] = sb + SM_XLO + boff;
    }

    float d[4][4];
    #pragma unroll
    for (int t = 0; t < 4; ++t)
        d[t][0] = d[t][1] = d[t][2] = d[t][3] = 0.f;

    #pragma unroll
    for (int c = 0; c < 9; ++c) {
        const uint32_t aoff = (uint32_t)c * 32u;             // 16 kk * 2B
        const uint32_t boff = (uint32_t)c * (16u * XST2 * 2u);
        uint32_t ah[2][4], al[2][4], bh[2][2], bl[2][2];
        #pragma unroll
        for (int mt = 0; mt < 2; ++mt) LDMX4(ah[mt], aHb[mt] + aoff);
        #pragma unroll
        for (int mt = 0; mt < 2; ++mt) LDMX4(al[mt], aLb[mt] + aoff);
        #pragma unroll
        for (int nti = 0; nti < 2; ++nti) LDMX2T(bh[nti], bHb[nti] + boff);
        #pragma unroll
        for (int nti = 0; nti < 2; ++nti) LDMX2T(bl[nti], bLb[nti] + boff);
        #pragma unroll
        for (int mt = 0; mt < 2; ++mt) {
            #pragma unroll
            for (int nti = 0; nti < 2; ++nti) {
                MMA(d[mt * 2 + nti], ah[mt], bh[nti]);
                MMA(d[mt * 2 + nti], ah[mt], bl[nti]);
                MMA(d[mt * 2 + nti], al[mt], bh[nti]);
            }
        }
    }

    // ---- epilogue: D[i, pos], pos flattened/contiguous ----
    const int qr = lane >> 2;
    const int qc = (lane & 3) * 2;
    #pragma unroll
    for (int mt = 0; mt < 2; ++mt) {
        #pragma unroll
        for (int nti = 0; nti < 2; ++nti) {
            const float* dd = d[mt * 2 + nti];
            int pos = pos0 + (warp * 2 + nti) * 8 + qc;
            if (pos < 3136) {
                int i = i0 + mt * 16 + qr;
                float* p = out + i * 3136 + pos;
                *(float2*)p = make_float2(dd[0], dd[1]);
                *(float2*)(p + 8 * 3136) = make_float2(dd[2], dd[3]);
            }
        }
    }
}

extern "C" void kernel_launch(void* const* d_in, const int* in_sizes, int n_in,
                              void* d_out, int out_size)
{
    const float* x = (const float*)d_in[0];   // 48*56*56
    const float* W = (const float*)d_in[1];   // 192*48*3
    float* out = (float*)d_out;               // 192*56*56

    static bool attr_set = false;
    if (!attr_set) {
        cudaFuncSetAttribute(gemm_kernel,
                             cudaFuncAttributeMaxDynamicSharedMemorySize, SM_TOTAL);
        attr_set = true;
    }
    const int total = NA + NB + NC;           // 61056
    conv_kernel<<<(total + NT - 1) / NT, NT>>>(x, W);
    dim3 grid(25, 6);
    gemm_kernel<<<grid, NT, SM_TOTAL>>>(out);
}